// round 1
// baseline (speedup 1.0000x reference)
#include <cuda_runtime.h>

// Problem constants (shapes fixed by the dataset)
#define B 16
#define F 256
#define T 8192
#define KKEEP 204   // k = int(256 * (1 - 0.2))

// Scratch for the per-(b,f) binary mask. 16*256 floats.
__device__ float g_mask[B * F];

// ---------------------------------------------------------------------------
// Kernel 1: compute binary[b,f].
// grid = B blocks, block = F threads. O(F^2) count per row in smem — trivial.
// kept(i) <=> #{j : x2[j] > x2[i]} < KKEEP   (tie-correct vs top_k kth value)
// binary = kept && (x2 > 0)                   (probs > 0.5 <=> wta > 0)
// ---------------------------------------------------------------------------
__global__ void mask_kernel(const float* __restrict__ w_mask,
                            const float* __restrict__ noise) {
    __shared__ float s[F];
    const int b = blockIdx.x;
    const int f = threadIdx.x;

    float w = w_mask[f];
    float sig = 1.0f / (1.0f + __expf(-w));
    // __expf precision (~2^-22 rel) is plenty for a 1e-3 check, but the
    // threshold comparison wants consistency across threads, which it has:
    // every thread computes its own x2 once and all comparisons use s[].
    float x2 = sig + 0.05f * noise[b * F + f];
    s[f] = x2;
    __syncthreads();

    int gt = 0;
#pragma unroll 8
    for (int j = 0; j < F; ++j) {
        gt += (s[j] > x2) ? 1 : 0;
    }
    float bin = (gt < KKEEP && x2 > 0.0f) ? 1.0f : 0.0f;
    g_mask[b * F + f] = bin;
}

// ---------------------------------------------------------------------------
// Kernel 2: masked_x[b,0,f,t] = binary[b,f] * x[b,0,f,t]
// float4 over B*F*T elements. T=8192 -> 2048 float4 per (b,f) row.
// One float4 per thread, exact mapping (no tail: counts are powers of two).
// ---------------------------------------------------------------------------
__global__ void masked_x_kernel(const float* __restrict__ x,
                                float* __restrict__ out) {
    const long long v = (long long)blockIdx.x * blockDim.x + threadIdx.x;
    // v in [0, B*F*T/4) = [0, 8388608)
    const int row = (int)(v >> 11);          // v / 2048 -> (b*F + f)
    const float m = __ldg(&g_mask[row]);
    float4 xv = ((const float4*)x)[v];
    xv.x *= m; xv.y *= m; xv.z *= m; xv.w *= m;
    ((float4*)out)[v] = xv;
}

// ---------------------------------------------------------------------------
// Kernel 3: binary_mask[b,0,t,f] = binary[b,f]  (write-only broadcast)
// float4 over B*T*F elements. F=256 -> 64 float4 per t-row, repeated T times.
// value = mask row b read as float4 at lane (v % 64).
// ---------------------------------------------------------------------------
__global__ void binary_mask_kernel(float* __restrict__ out) {
    const long long v = (long long)blockIdx.x * blockDim.x + threadIdx.x;
    // v in [0, B*T*F/4) = [0, 8388608). Per-b chunk = T*F/4 = 524288.
    const int b  = (int)(v >> 19);           // v / 524288
    const int f4 = (int)(v & 63);            // (v % 64) float4 lane within F
    const float4 m4 = __ldg(&((const float4*)g_mask)[b * (F / 4) + f4]);
    ((float4*)out)[v] = m4;
}

extern "C" void kernel_launch(void* const* d_in, const int* in_sizes, int n_in,
                              void* d_out, int out_size) {
    const float* x      = (const float*)d_in[0];   // (16,1,256,8192) f32
    const float* w_mask = (const float*)d_in[1];   // (1,1,1,256)     f32
    const float* noise  = (const float*)d_in[2];   // (16,1,1,256)    f32
    float* out = (float*)d_out;

    const long long n1 = (long long)B * F * T;     // 33,554,432 (masked_x)

    // 1) tiny mask computation
    mask_kernel<<<B, F>>>(w_mask, noise);

    // 2) masked_x stream: n1/4 float4, 256 threads/block -> 32768 blocks
    {
        const int threads = 256;
        const long long n4 = n1 / 4;
        const int blocks = (int)(n4 / threads);    // exact (power of two)
        masked_x_kernel<<<blocks, threads>>>(x, out);
    }

    // 3) binary_mask stream (only if the harness output holds both tensors)
    if ((long long)out_size >= 2 * n1) {
        const int threads = 256;
        const long long n4 = n1 / 4;
        const int blocks = (int)(n4 / threads);
        binary_mask_kernel<<<blocks, threads>>>(out + n1);
    }
}

// round 2
// speedup vs baseline: 1.2200x; 1.2200x over previous
#include <cuda_runtime.h>

// Problem constants (shapes fixed by the dataset)
#define B 16
#define F 256
#define T 8192
#define KKEEP 204   // k = int(256 * (1 - 0.2))

#define N1 (B * F * T)          // 33,554,432 floats per output tensor
#define N4_MASKED (N1 / 4)      // 8,388,608 float4 (masked_x half)

// Scratch for the per-(b,f) binary mask. 16*256 floats.
__device__ float g_mask[B * F];

// ---------------------------------------------------------------------------
// Kernel 1: compute binary[b,f].
// grid = B blocks, block = F threads. O(F^2) count per row in smem — trivial.
// kept(i) <=> #{j : x2[j] > x2[i]} < KKEEP   (tie-correct vs top_k kth value)
// binary = kept && (x2 > 0)                   (probs > 0.5 <=> wta > 0)
// ---------------------------------------------------------------------------
__global__ void mask_kernel(const float* __restrict__ w_mask,
                            const float* __restrict__ noise) {
    __shared__ float s[F];
    const int b = blockIdx.x;
    const int f = threadIdx.x;

    float w = w_mask[f];
    float sig = 1.0f / (1.0f + __expf(-w));
    float x2 = sig + 0.05f * noise[b * F + f];
    s[f] = x2;
    __syncthreads();

    int gt = 0;
#pragma unroll 8
    for (int j = 0; j < F; ++j) {
        gt += (s[j] > x2) ? 1 : 0;
    }
    float bin = (gt < KKEEP && x2 > 0.0f) ? 1.0f : 0.0f;
    g_mask[b * F + f] = bin;
}

// ---------------------------------------------------------------------------
// Kernel 2 (merged streamer), linear float4 index space of size n4_total:
//   v <  N4_MASKED : masked_x[b,0,f,t] = binary[b,f] * x[b,0,f,t]
//                    row = v >> 11 (2048 float4 per (b,f) row)
//   v >= N4_MASKED : binary_mask[b,0,t,f] = binary[b,f]  (write-only pattern)
//                    w = v - N4_MASKED; b = w >> 19; f4 = w & 63
// ILP = 4 float4 per thread, coalesced within each sub-iteration.
// Streaming hints: __ldcs on x, __stcs on out (no reuse anywhere).
// ---------------------------------------------------------------------------
__global__ void stream_kernel(const float4* __restrict__ x,
                              float4* __restrict__ out,
                              int n4_total) {
    const int base = blockIdx.x * (blockDim.x * 4) + threadIdx.x;
    const float4* gm4 = (const float4*)g_mask;

#pragma unroll
    for (int k = 0; k < 4; ++k) {
        const int v = base + k * blockDim.x;
        if (v >= n4_total) break;   // uniform across block for the tail only
        if (v < N4_MASKED) {
            const int row = v >> 11;                 // (b*F + f)
            const float m = __ldg(&g_mask[row]);     // L1-resident broadcast
            float4 xv = __ldcs(&x[v]);               // stream read, no reuse
            xv.x *= m; xv.y *= m; xv.z *= m; xv.w *= m;
            __stcs(&out[v], xv);
        } else {
            const int w  = v - N4_MASKED;
            const int b  = w >> 19;                  // T*F/4 = 524288 per batch
            const int f4 = w & 63;                   // float4 lane within F
            const float4 m4 = __ldg(&gm4[(b << 6) + f4]);
            __stcs(&out[v], m4);
        }
    }
}

extern "C" void kernel_launch(void* const* d_in, const int* in_sizes, int n_in,
                              void* d_out, int out_size) {
    const float* x      = (const float*)d_in[0];   // (16,1,256,8192) f32
    const float* w_mask = (const float*)d_in[1];   // (1,1,1,256)     f32
    const float* noise  = (const float*)d_in[2];   // (16,1,1,256)    f32
    float* out = (float*)d_out;

    // 1) tiny mask computation (serial dependency, ~4k elements)
    mask_kernel<<<B, F>>>(w_mask, noise);

    // 2) one merged streamer over the whole output
    long long n4_ll = (long long)out_size / 4;
    if (n4_ll > 2LL * N4_MASKED) n4_ll = 2LL * N4_MASKED;
    const int n4_total = (int)n4_ll;                 // <= 16,777,216
    const int threads = 256;
    const int per_block = threads * 4;               // 1024 float4 per block
    const int blocks = (n4_total + per_block - 1) / per_block;
    stream_kernel<<<blocks, threads>>>((const float4*)x, (float4*)out, n4_total);
}